// round 8
// baseline (speedup 1.0000x reference)
#include <cuda_runtime.h>

// Vanilla tanh RNN: B=4096, T=2048, I=4, H=20, O=4.
// R8: TWO independent batch-chains per warp (6 batches/warp, 30/32 lanes live).
// Chains A and B interleave in the instruction stream -> intra-warp ILP covers
// the LDS/fma/tanh latency of each chain. Warp count halves (683), per-warp
// fixed costs halve chip-wide. 5 warps/CTA, grid=137 (1 CTA/SM).
// Keeps: f32x2 dot packed over j, tanh.approx, syncwarp-free ping-pong exchange,
// unconditional stores (dead lanes -> scratch), register x-prefetch rings.

#define B_TOTAL 4096
#define T_STEPS 2048
#define H_DIM   20
#define O_DIM   4
#define WARPS_CTA 5
#define NB_WARP   6          // 3 per chain
#define NB_CTA    (WARPS_CTA * NB_WARP)   // 30
#define CTA_THREADS (WARPS_CTA * 32)
#define GRID 137             // ceil(4096/30)
#define PF 4                 // x prefetch depth per chain (rounds)

typedef unsigned long long u64;

__device__ __forceinline__ u64 pack2(float lo, float hi) {
    u64 r; asm("mov.b64 %0, {%1,%2};" : "=l"(r) : "f"(lo), "f"(hi)); return r;
}
__device__ __forceinline__ void unpack2(u64 v, float& lo, float& hi) {
    asm("mov.b64 {%0,%1}, %2;" : "=f"(lo), "=f"(hi) : "l"(v));
}
__device__ __forceinline__ u64 fma2(u64 a, u64 b, u64 c) {
    u64 d; asm("fma.rn.f32x2 %0, %1, %2, %3;" : "=l"(d) : "l"(a), "l"(b), "l"(c)); return d;
}
__device__ __forceinline__ u64 add2(u64 a, u64 b) {
    u64 d; asm("add.rn.f32x2 %0, %1, %2;" : "=l"(d) : "l"(a), "l"(b)); return d;
}
__device__ __forceinline__ float tanha(float x) {
    float r; asm("tanh.approx.f32 %0, %1;" : "=f"(r) : "f"(x)); return r;
}

// One interleaved round: one step of chain A and one of chain B.
// Branch-free; unconditional stores (sOff routes dead lanes to scratch words).
__device__ __forceinline__ void rnn_round(
    const float* __restrict__ srcA, float* __restrict__ dstA,
    const float* __restrict__ srcB, float* __restrict__ dstB,
    int g, int sOff, ulonglong2 xvA, ulonglong2 xvB,
    const u64* __restrict__ W0, const u64* __restrict__ W1,
    ulonglong2 Wi0, ulonglong2 Wi1, u64 seed0, u64 seed1)
{
    const ulonglong2* hA = reinterpret_cast<const ulonglong2*>(srcA + g * H_DIM);
    const ulonglong2* hB = reinterpret_cast<const ulonglong2*>(srcB + g * H_DIM);
    ulonglong2 a0v = hA[0], a1v = hA[1], a2v = hA[2], a3v = hA[3], a4v = hA[4];
    ulonglong2 b0v = hB[0], b1v = hB[1], b2v = hB[2], b3v = hB[3], b4v = hB[4];

    const u64 z = pack2(0.f, 0.f);
    // Chain A accumulators (2 per output pair) and chain B accumulators.
    u64 Aa0 = fma2(xvA.x, Wi0.x, seed0);
    u64 Ab0 = fma2(xvA.y, Wi0.y, z);
    u64 Aa1 = fma2(xvA.x, Wi1.x, seed1);
    u64 Ab1 = fma2(xvA.y, Wi1.y, z);
    u64 Ba0 = fma2(xvB.x, Wi0.x, seed0);
    u64 Bb0 = fma2(xvB.y, Wi0.y, z);
    u64 Ba1 = fma2(xvB.x, Wi1.x, seed1);
    u64 Bb1 = fma2(xvB.y, Wi1.y, z);

    Aa0 = fma2(a0v.x, W0[0], Aa0);  Ab0 = fma2(a0v.y, W0[1], Ab0);
    Aa1 = fma2(a0v.x, W1[0], Aa1);  Ab1 = fma2(a0v.y, W1[1], Ab1);
    Ba0 = fma2(b0v.x, W0[0], Ba0);  Bb0 = fma2(b0v.y, W0[1], Bb0);
    Ba1 = fma2(b0v.x, W1[0], Ba1);  Bb1 = fma2(b0v.y, W1[1], Bb1);

    Aa0 = fma2(a1v.x, W0[2], Aa0);  Ab0 = fma2(a1v.y, W0[3], Ab0);
    Aa1 = fma2(a1v.x, W1[2], Aa1);  Ab1 = fma2(a1v.y, W1[3], Ab1);
    Ba0 = fma2(b1v.x, W0[2], Ba0);  Bb0 = fma2(b1v.y, W0[3], Bb0);
    Ba1 = fma2(b1v.x, W1[2], Ba1);  Bb1 = fma2(b1v.y, W1[3], Bb1);

    Aa0 = fma2(a2v.x, W0[4], Aa0);  Ab0 = fma2(a2v.y, W0[5], Ab0);
    Aa1 = fma2(a2v.x, W1[4], Aa1);  Ab1 = fma2(a2v.y, W1[5], Ab1);
    Ba0 = fma2(b2v.x, W0[4], Ba0);  Bb0 = fma2(b2v.y, W0[5], Bb0);
    Ba1 = fma2(b2v.x, W1[4], Ba1);  Bb1 = fma2(b2v.y, W1[5], Bb1);

    Aa0 = fma2(a3v.x, W0[6], Aa0);  Ab0 = fma2(a3v.y, W0[7], Ab0);
    Aa1 = fma2(a3v.x, W1[6], Aa1);  Ab1 = fma2(a3v.y, W1[7], Ab1);
    Ba0 = fma2(b3v.x, W0[6], Ba0);  Bb0 = fma2(b3v.y, W0[7], Bb0);
    Ba1 = fma2(b3v.x, W1[6], Ba1);  Bb1 = fma2(b3v.y, W1[7], Bb1);

    Aa0 = fma2(a4v.x, W0[8], Aa0);  Ab0 = fma2(a4v.y, W0[9], Ab0);
    Aa1 = fma2(a4v.x, W1[8], Aa1);  Ab1 = fma2(a4v.y, W1[9], Ab1);
    Ba0 = fma2(b4v.x, W0[8], Ba0);  Bb0 = fma2(b4v.y, W0[9], Bb0);
    Ba1 = fma2(b4v.x, W1[8], Ba1);  Bb1 = fma2(b4v.y, W1[9], Bb1);

    u64 As0 = add2(Aa0, Ab0);
    u64 As1 = add2(Aa1, Ab1);
    u64 Bs0 = add2(Ba0, Bb0);
    u64 Bs1 = add2(Ba1, Bb1);

    float x0, x1, y0, y1;
    unpack2(As0, x0, x1);
    unpack2(As1, y0, y1);
    float tA0 = tanha(x0 + x1);
    float tA1 = tanha(y0 + y1);
    unpack2(Bs0, x0, x1);
    unpack2(Bs1, y0, y1);
    float tB0 = tanha(x0 + x1);
    float tB1 = tanha(y0 + y1);

    *reinterpret_cast<u64*>(dstA + sOff) = pack2(tA0, tA1);
    *reinterpret_cast<u64*>(dstB + sOff) = pack2(tB0, tB1);
    asm volatile("" ::: "memory");   // pin program order of smem ops across rounds
}

__global__ void __launch_bounds__(CTA_THREADS, 1)
rnn_tanh_kernel(
    const float* __restrict__ x,     const float* __restrict__ h0,
    const float* __restrict__ W_ih,  const float* __restrict__ W_hh,
    const float* __restrict__ b_ih,  const float* __restrict__ b_hh,
    const float* __restrict__ fc_w,  const float* __restrict__ fc_b,
    float* __restrict__ out)
{
    __shared__ __align__(128) float sm[WARPS_CTA][2][2][64];  // [warp][chain][pp][64]

    const int lane = threadIdx.x & 31;
    const int w    = threadIdx.x >> 5;
    const int base = blockIdx.x * NB_CTA + w * NB_WARP;
    if (base >= B_TOTAL) return;                     // fully dead warp

    const bool live = (lane < 30);
    const int  g    = live ? (lane / 10) : 2;
    const int  p    = live ? (lane % 10) : (lane - 30);
    const int  o0   = 2 * p;
    const int  sOff = live ? (g * H_DIM + o0) : (60 + (lane - 30) * 2);

    const int bA = base + g;                         // chain A batch
    const int bB = base + 3 + g;                     // chain B batch
    const int bAc = (bA < B_TOTAL) ? bA : (B_TOTAL - 1);
    const int bBc = (bB < B_TOTAL) ? bB : (B_TOTAL - 1);

    // ---- per-thread weights (packed over j; shared by both chains) ----
    const u64* whh = reinterpret_cast<const u64*>(W_hh);
    u64 W0[10], W1[10];
    #pragma unroll
    for (int q = 0; q < 10; q++) {
        W0[q] = __ldg(&whh[o0 * 10 + q]);
        W1[q] = __ldg(&whh[(o0 + 1) * 10 + q]);
    }
    const ulonglong2* wih = reinterpret_cast<const ulonglong2*>(W_ih);
    ulonglong2 Wi0 = __ldg(&wih[o0]);
    ulonglong2 Wi1 = __ldg(&wih[o0 + 1]);
    const float bias0 = __ldg(&b_ih[o0])     + __ldg(&b_hh[o0]);
    const float bias1 = __ldg(&b_ih[o0 + 1]) + __ldg(&b_hh[o0 + 1]);
    const u64 seed0 = pack2(bias0, 0.f);
    const u64 seed1 = pack2(bias1, 0.f);

    float* A0 = &sm[w][0][0][0];   // chain A ping
    float* A1 = &sm[w][0][1][0];   // chain A pong
    float* B0 = &sm[w][1][0][0];   // chain B ping
    float* B1 = &sm[w][1][1][0];   // chain B pong

    // ---- init h (plain layout) into ping buffers ----
    {
        const float2* h2 = reinterpret_cast<const float2*>(h0);
        float2 ha = __ldg(&h2[bAc * (H_DIM / 2) + p]);
        float2 hb = __ldg(&h2[bBc * (H_DIM / 2) + p]);
        *reinterpret_cast<u64*>(A0 + sOff) = pack2(ha.x, ha.y);
        *reinterpret_cast<u64*>(B0 + sOff) = pack2(hb.x, hb.y);
    }
    __syncwarp();

    // x rings, one per chain. x[b][t] = 16B.
    const ulonglong2* xpA = reinterpret_cast<const ulonglong2*>(x) + (size_t)bAc * T_STEPS;
    const ulonglong2* xpB = reinterpret_cast<const ulonglong2*>(x) + (size_t)bBc * T_STEPS;
    ulonglong2 xa[PF], xb[PF];
    #pragma unroll
    for (int q = 0; q < PF; q++) { xa[q] = __ldg(&xpA[q]); xb[q] = __ldg(&xpB[q]); }

    // Main loop (prefetch unclamped: t+q+PF <= T-1 for t <= T-2*PF).
    for (int t = 0; t < T_STEPS - PF; t += PF) {
        #pragma unroll
        for (int q = 0; q < PF; q++) {
            ulonglong2 xvA = xa[q], xvB = xb[q];
            xa[q] = __ldg(&xpA[t + q + PF]);
            xb[q] = __ldg(&xpB[t + q + PF]);
            if (q & 1)
                rnn_round(A1, A0, B1, B0, g, sOff, xvA, xvB, W0, W1, Wi0, Wi1, seed0, seed1);
            else
                rnn_round(A0, A1, B0, B1, g, sOff, xvA, xvB, W0, W1, Wi0, Wi1, seed0, seed1);
        }
    }
    // Epilogue: last PF rounds, no prefetch.
    #pragma unroll
    for (int q = 0; q < PF; q++) {
        if (q & 1)
            rnn_round(A1, A0, B1, B0, g, sOff, xa[q], xb[q], W0, W1, Wi0, Wi1, seed0, seed1);
        else
            rnn_round(A0, A1, B0, B1, g, sOff, xa[q], xb[q], W0, W1, Wi0, Wi1, seed0, seed1);
    }

    // Final h in ping buffers (T_STEPS even). Linear head: live lanes with p < 4.
    __syncwarp();
    if (live && p < O_DIM) {
        float accA = __ldg(&fc_b[p]);
        float accB = accA;
        const float* hfA = A0 + g * H_DIM;
        const float* hfB = B0 + g * H_DIM;
        #pragma unroll
        for (int j = 0; j < H_DIM; j++) {
            float wj = __ldg(&fc_w[p * H_DIM + j]);
            accA = fmaf(hfA[j], wj, accA);
            accB = fmaf(hfB[j], wj, accB);
        }
        if (bA < B_TOTAL) out[bA * O_DIM + p] = accA;
        if (bB < B_TOTAL) out[bB * O_DIM + p] = accB;
    }
}

extern "C" void kernel_launch(void* const* d_in, const int* in_sizes, int n_in,
                              void* d_out, int out_size)
{
    const float* x    = (const float*)d_in[0];
    const float* h0   = (const float*)d_in[1];
    const float* W_ih = (const float*)d_in[2];
    const float* W_hh = (const float*)d_in[3];
    const float* b_ih = (const float*)d_in[4];
    const float* b_hh = (const float*)d_in[5];
    const float* fc_w = (const float*)d_in[6];
    const float* fc_b = (const float*)d_in[7];
    float* out = (float*)d_out;

    rnn_tanh_kernel<<<GRID, CTA_THREADS>>>(x, h0, W_ih, W_hh, b_ih, b_hh,
                                           fc_w, fc_b, out);
}

// round 9
// speedup vs baseline: 1.1006x; 1.1006x over previous
#include <cuda_runtime.h>

// Vanilla tanh RNN: B=4096, T=2048, I=4, H=20, O=4.
// R9: register-only recurrence. h exchanged via __shfl_sync within the batch group
// (lane q of group g holds {h_2q, h_2q+1}); no SMEM/LSU in the time loop at all.
// Shell: 10 warps/CTA, 3 batches/warp (30/32 lanes live), f32x2 dot packed over j,
// tanh.approx, 8-deep x register prefetch ring. grid=148 (1 CTA/SM).

#define B_TOTAL 4096
#define T_STEPS 2048
#define H_DIM   20
#define O_DIM   4
#define WARPS_CTA 10
#define CTA_THREADS (WARPS_CTA * 32)
#define GRID 148
#define PF 8                       // x prefetch depth (steps)

typedef unsigned long long u64;

__device__ __forceinline__ u64 pack2(float lo, float hi) {
    u64 r; asm("mov.b64 %0, {%1,%2};" : "=l"(r) : "f"(lo), "f"(hi)); return r;
}
__device__ __forceinline__ void unpack2(u64 v, float& lo, float& hi) {
    asm("mov.b64 {%0,%1}, %2;" : "=f"(lo), "=f"(hi) : "l"(v));
}
__device__ __forceinline__ u64 fma2(u64 a, u64 b, u64 c) {
    u64 d; asm("fma.rn.f32x2 %0, %1, %2, %3;" : "=l"(d) : "l"(a), "l"(b), "l"(c)); return d;
}
__device__ __forceinline__ u64 add2(u64 a, u64 b) {
    u64 d; asm("add.rn.f32x2 %0, %1, %2;" : "=l"(d) : "l"(a), "l"(b)); return d;
}
__device__ __forceinline__ float tanha(float x) {
    float r; asm("tanh.approx.f32 %0, %1;" : "=f"(r) : "f"(x)); return r;
}

// One step: broadcast the group's 10 h-pairs via shfl, dot, tanh, update own pair.
// Pure registers; warp must be converged (it is: no divergence in the loop).
__device__ __forceinline__ void rnn_step(
    u64& hpair, int sbase, ulonglong2 xv,
    const u64* __restrict__ W0, const u64* __restrict__ W1,
    ulonglong2 Wi0, ulonglong2 Wi1, u64 seed0, u64 seed1)
{
    // Gather all 10 pairs of this batch group (10 u64 = 20 SHFL.b32, independent).
    u64 hk0 = __shfl_sync(0xffffffffu, hpair, sbase + 0);
    u64 hk1 = __shfl_sync(0xffffffffu, hpair, sbase + 1);
    u64 hk2 = __shfl_sync(0xffffffffu, hpair, sbase + 2);
    u64 hk3 = __shfl_sync(0xffffffffu, hpair, sbase + 3);
    u64 hk4 = __shfl_sync(0xffffffffu, hpair, sbase + 4);
    u64 hk5 = __shfl_sync(0xffffffffu, hpair, sbase + 5);
    u64 hk6 = __shfl_sync(0xffffffffu, hpair, sbase + 6);
    u64 hk7 = __shfl_sync(0xffffffffu, hpair, sbase + 7);
    u64 hk8 = __shfl_sync(0xffffffffu, hpair, sbase + 8);
    u64 hk9 = __shfl_sync(0xffffffffu, hpair, sbase + 9);

    const u64 z = pack2(0.f, 0.f);
    // 4 independent f32x2 chains (2 per output); x/bias seeds issue before shfl results land.
    u64 a0 = fma2(xv.x, Wi0.x, seed0);
    u64 b0 = fma2(xv.y, Wi0.y, z);
    u64 a1 = fma2(xv.x, Wi1.x, seed1);
    u64 b1 = fma2(xv.y, Wi1.y, z);

    a0 = fma2(hk0, W0[0], a0);  b0 = fma2(hk1, W0[1], b0);
    a1 = fma2(hk0, W1[0], a1);  b1 = fma2(hk1, W1[1], b1);
    a0 = fma2(hk2, W0[2], a0);  b0 = fma2(hk3, W0[3], b0);
    a1 = fma2(hk2, W1[2], a1);  b1 = fma2(hk3, W1[3], b1);
    a0 = fma2(hk4, W0[4], a0);  b0 = fma2(hk5, W0[5], b0);
    a1 = fma2(hk4, W1[4], a1);  b1 = fma2(hk5, W1[5], b1);
    a0 = fma2(hk6, W0[6], a0);  b0 = fma2(hk7, W0[7], b0);
    a1 = fma2(hk6, W1[6], a1);  b1 = fma2(hk7, W1[7], b1);
    a0 = fma2(hk8, W0[8], a0);  b0 = fma2(hk9, W0[9], b0);
    a1 = fma2(hk8, W1[8], a1);  b1 = fma2(hk9, W1[9], b1);

    u64 s0 = add2(a0, b0);
    u64 s1 = add2(a1, b1);

    float l0, l1, m0, m1;
    unpack2(s0, l0, l1);
    unpack2(s1, m0, m1);
    float t0 = tanha(l0 + l1);
    float t1 = tanha(m0 + m1);
    hpair = pack2(t0, t1);
}

__global__ void __launch_bounds__(CTA_THREADS, 1)
rnn_tanh_kernel(
    const float* __restrict__ x,     const float* __restrict__ h0,
    const float* __restrict__ W_ih,  const float* __restrict__ W_hh,
    const float* __restrict__ b_ih,  const float* __restrict__ b_hh,
    const float* __restrict__ fc_w,  const float* __restrict__ fc_b,
    float* __restrict__ out)
{
    __shared__ __align__(16) float smh[WARPS_CTA][3][H_DIM];  // final h staging only

    const int lane = threadIdx.x & 31;
    const int w    = threadIdx.x >> 5;
    const int gw   = blockIdx.x * WARPS_CTA + w;     // global warp id
    if (gw * 3 >= B_TOTAL) return;                   // whole warp idle

    const bool live  = (lane < 30);
    const int  g     = live ? (lane / 10) : 2;       // batch group (lanes 30/31 ride group 2)
    const int  p     = live ? (lane % 10) : (lane - 30);
    const int  sbase = g * 10;                       // group's base lane for shfl
    const int  b     = gw * 3 + g;
    const int  bc    = (b < B_TOTAL) ? b : (B_TOTAL - 1);
    const int  o0    = 2 * p;                        // owned outputs o0, o0+1

    // ---- per-thread weights (packed over j) ----
    const u64* whh = reinterpret_cast<const u64*>(W_hh);   // row = 10 u64 pairs
    u64 W0[10], W1[10];
    #pragma unroll
    for (int q = 0; q < 10; q++) {
        W0[q] = __ldg(&whh[o0 * 10 + q]);
        W1[q] = __ldg(&whh[(o0 + 1) * 10 + q]);
    }
    const ulonglong2* wih = reinterpret_cast<const ulonglong2*>(W_ih);  // row = 16B
    ulonglong2 Wi0 = __ldg(&wih[o0]);
    ulonglong2 Wi1 = __ldg(&wih[o0 + 1]);
    const float bias0 = __ldg(&b_ih[o0])     + __ldg(&b_hh[o0]);
    const float bias1 = __ldg(&b_ih[o0 + 1]) + __ldg(&b_hh[o0 + 1]);
    const u64 seed0 = pack2(bias0, 0.f);
    const u64 seed1 = pack2(bias1, 0.f);

    // ---- init own h pair in a register ----
    u64 hpair;
    {
        const float2* h2 = reinterpret_cast<const float2*>(h0);
        float2 hv = __ldg(&h2[bc * (H_DIM / 2) + p]);
        hpair = pack2(hv.x, hv.y);
    }

    // x[b][t] = 4 floats = one ulonglong2. 8-deep register prefetch ring.
    const ulonglong2* xp = reinterpret_cast<const ulonglong2*>(x) + (size_t)bc * T_STEPS;
    ulonglong2 xbuf[PF];
    #pragma unroll
    for (int q = 0; q < PF; q++) xbuf[q] = __ldg(&xp[q]);

    // Main loop: prefetch unclamped (t+q+PF <= T-1 for t <= T-2*PF).
    for (int t = 0; t < T_STEPS - PF; t += PF) {
        #pragma unroll
        for (int q = 0; q < PF; q++) {
            ulonglong2 xv = xbuf[q];
            xbuf[q] = __ldg(&xp[t + q + PF]);
            rnn_step(hpair, sbase, xv, W0, W1, Wi0, Wi1, seed0, seed1);
        }
    }
    // Epilogue: last PF steps, no prefetch.
    #pragma unroll
    for (int q = 0; q < PF; q++)
        rnn_step(hpair, sbase, xbuf[q], W0, W1, Wi0, Wi1, seed0, seed1);

    // Stage final h to SMEM once, then linear head (live lanes with p < 4).
    if (live) *reinterpret_cast<u64*>(&smh[w][g][o0]) = hpair;
    __syncwarp();
    if (live && p < O_DIM && b < B_TOTAL) {
        const float* hf = &smh[w][g][0];
        float acc = __ldg(&fc_b[p]);
        #pragma unroll
        for (int j = 0; j < H_DIM; j++)
            acc = fmaf(hf[j], __ldg(&fc_w[p * H_DIM + j]), acc);
        out[b * O_DIM + p] = acc;
    }
}

extern "C" void kernel_launch(void* const* d_in, const int* in_sizes, int n_in,
                              void* d_out, int out_size)
{
    const float* x    = (const float*)d_in[0];
    const float* h0   = (const float*)d_in[1];
    const float* W_ih = (const float*)d_in[2];
    const float* W_hh = (const float*)d_in[3];
    const float* b_ih = (const float*)d_in[4];
    const float* b_hh = (const float*)d_in[5];
    const float* fc_w = (const float*)d_in[6];
    const float* fc_b = (const float*)d_in[7];
    float* out = (float*)d_out;

    rnn_tanh_kernel<<<GRID, CTA_THREADS>>>(x, h0, W_ih, W_hh, b_ih, b_hh,
                                           fc_w, fc_b, out);
}